// round 1
// baseline (speedup 1.0000x reference)
#include <cuda_runtime.h>

#define NV 100000
#define ME 50000
#define D  128
#define WMED (1.0f / 13.0f)

// ---------------- scratch (device globals; no runtime allocation) ----------------
__device__ float g_Y[(size_t)NV * D];   // Y, then Xs in-place
__device__ float g_deg[NV];
__device__ float g_dinv[NV];
__device__ int   g_pair[ME];
__device__ const int* g_verts;          // selected vertex array (vs. 'edges')

// ---------------- small float4 helpers ----------------
__device__ __forceinline__ float4 f4add(float4 a, float4 b) {
    return make_float4(a.x + b.x, a.y + b.y, a.z + b.z, a.w + b.w);
}
__device__ __forceinline__ float4 f4scale(float4 a, float s) {
    return make_float4(a.x * s, a.y * s, a.z * s, a.w * s);
}

__device__ __forceinline__ void red_add_v4(float* p, float4 v) {
    asm volatile("red.global.add.v4.f32 [%0], {%1,%2,%3,%4};"
                 :: "l"(p), "f"(v.x), "f"(v.y), "f"(v.z), "f"(v.w) : "memory");
}

__device__ __forceinline__ float warp_sum(float v) {
#pragma unroll
    for (int o = 16; o > 0; o >>= 1) v += __shfl_xor_sync(0xffffffffu, v, o);
    return v;
}

// ---------------- K1: Y = X @ W + b (fp32) ----------------
// BM=128, BN=128, BK=32, 256 threads, 8x8 per-thread register tile.
__global__ void __launch_bounds__(256) k_gemm(const float* __restrict__ X,
                                              const float* __restrict__ Wm,
                                              const float* __restrict__ bias) {
    __shared__ float sA[32][132];   // transposed X tile: sA[k][row]
    __shared__ float sB[32][132];   // W tile: sB[k][col]
    const int tid  = threadIdx.x;
    const int row0 = blockIdx.x * 128;
    const int tx   = tid & 15;      // col group
    const int ty   = tid >> 4;      // row group

    float acc[8][8];
#pragma unroll
    for (int r = 0; r < 8; r++)
#pragma unroll
        for (int c = 0; c < 8; c++) acc[r][c] = 0.f;

    for (int k0 = 0; k0 < D; k0 += 32) {
        // load X tile (128 rows x 32 k) and W tile (32 k x 128 cols)
#pragma unroll
        for (int i = 0; i < 4; i++) {
            int idx = tid + i * 256;          // 0..1023 float4s
            int r   = idx >> 3;               // 0..127 row
            int kq  = idx & 7;                // float4 along k
            int gr  = row0 + r;
            float4 xv = make_float4(0.f, 0.f, 0.f, 0.f);
            if (gr < NV) xv = *(const float4*)&X[(size_t)gr * D + k0 + kq * 4];
            sA[kq * 4 + 0][r] = xv.x;
            sA[kq * 4 + 1][r] = xv.y;
            sA[kq * 4 + 2][r] = xv.z;
            sA[kq * 4 + 3][r] = xv.w;

            int kk = idx >> 5;                // 0..31 k
            int cq = idx & 31;                // float4 along col
            *(float4*)&sB[kk][cq * 4] = *(const float4*)&Wm[(size_t)(k0 + kk) * D + cq * 4];
        }
        __syncthreads();

#pragma unroll 8
        for (int k = 0; k < 32; k++) {
            float4 a0 = *(const float4*)&sA[k][ty * 4];
            float4 a1 = *(const float4*)&sA[k][64 + ty * 4];
            float4 b0 = *(const float4*)&sB[k][tx * 4];
            float4 b1 = *(const float4*)&sB[k][64 + tx * 4];
            float a[8]  = {a0.x, a0.y, a0.z, a0.w, a1.x, a1.y, a1.z, a1.w};
            float bb[8] = {b0.x, b0.y, b0.z, b0.w, b1.x, b1.y, b1.z, b1.w};
#pragma unroll
            for (int r = 0; r < 8; r++)
#pragma unroll
                for (int c = 0; c < 8; c++) acc[r][c] += a[r] * bb[c];
        }
        __syncthreads();
    }

    float4 bv0 = *(const float4*)&bias[tx * 4];
    float4 bv1 = *(const float4*)&bias[64 + tx * 4];
#pragma unroll
    for (int r = 0; r < 8; r++) {
        int lr = (r < 4) ? (ty * 4 + r) : (64 + ty * 4 + (r - 4));
        int gr = row0 + lr;
        if (gr >= NV) continue;
        float4 o0 = make_float4(acc[r][0] + bv0.x, acc[r][1] + bv0.y,
                                acc[r][2] + bv0.z, acc[r][3] + bv0.w);
        float4 o1 = make_float4(acc[r][4] + bv1.x, acc[r][5] + bv1.y,
                                acc[r][6] + bv1.z, acc[r][7] + bv1.w);
        *(float4*)&g_Y[(size_t)gr * D + tx * 4]      = o0;
        *(float4*)&g_Y[(size_t)gr * D + 64 + tx * 4] = o1;
    }
}

// ---------------- K0: deg init + vertex-array selection ----------------
__global__ void k_deginit(const int* __restrict__ c0, const int* __restrict__ c1) {
    int i = blockIdx.x * blockDim.x + threadIdx.x;
    if (i < NV) g_deg[i] = 1.0f;
    if (i == 0) {
        // 'edges' = repeat(arange(M), 8): first 8 entries 0, next 8 entries 1.
        bool c0_is_edges = (c0[0] == 0 && c0[1] == 0 && c0[8] == 1 && c0[9] == 1);
        g_verts = c0_is_edges ? c1 : c0;
    }
}

// ---------------- K2: per-hyperedge argmax pair + degree atomics ----------------
__global__ void __launch_bounds__(256) k_edge() {
    int w    = (blockIdx.x * blockDim.x + threadIdx.x) >> 5;
    int lane = threadIdx.x & 31;
    if (w >= ME) return;
    const int* verts = g_verts;

    int4 p0 = ((const int4*)(verts + w * 8))[0];
    int4 p1 = ((const int4*)(verts + w * 8))[1];
    int v[8] = {p0.x, p0.y, p0.z, p0.w, p1.x, p1.y, p1.z, p1.w};

    float4 f[8];
#pragma unroll
    for (int j = 0; j < 8; j++)
        f[j] = *(const float4*)&g_Y[(size_t)v[j] * D + lane * 4];

    float sq[8];
#pragma unroll
    for (int j = 0; j < 8; j++)
        sq[j] = warp_sum(f[j].x * f[j].x + f[j].y * f[j].y +
                         f[j].z * f[j].z + f[j].w * f[j].w);

    float best = -1e30f;
    int bu = 0, bv = 1;
#pragma unroll
    for (int j = 0; j < 8; j++) {
#pragma unroll
        for (int l = j + 1; l < 8; l++) {
            float d = warp_sum(f[j].x * f[l].x + f[j].y * f[l].y +
                               f[j].z * f[l].z + f[j].w * f[l].w);
            float d2 = sq[j] + sq[l] - 2.0f * d;
            if (d2 > best) { best = d2; bu = j; bv = l; }   // first-occurrence, row-major
        }
    }

    if (lane < 8) {
        float wd = (lane == bu || lane == bv) ? 7.0f * WMED : 2.0f * WMED;
        atomicAdd(&g_deg[v[lane]], wd);
    }
    if (lane == 0) g_pair[w] = bu | (bv << 4);
}

// ---------------- K3: dinv = rsqrt(deg); Xs = Y*dinv (in place); out = Xs ----------------
__global__ void k_scale(float* __restrict__ out) {
    int i = blockIdx.x * blockDim.x + threadIdx.x;   // one float4 each, NV*32 total
    if (i >= NV * (D / 4)) return;
    int row = i >> 5;
    float dg = g_deg[row];
    float rs = rsqrtf(dg);
    rs = rs * (1.5f - 0.5f * dg * rs * rs);          // Newton refine
    if ((i & 31) == 0) g_dinv[row] = rs;
    float4 y = ((float4*)g_Y)[i];
    y = f4scale(y, rs);
    ((float4*)g_Y)[i] = y;
    ((float4*)out)[i] = y;
}

// ---------------- K4: scatter graph-edge contributions ----------------
__global__ void __launch_bounds__(256) k_scatter(float* __restrict__ out) {
    int w    = (blockIdx.x * blockDim.x + threadIdx.x) >> 5;
    int lane = threadIdx.x & 31;
    if (w >= ME) return;
    const int* verts = g_verts;

    int4 p0 = ((const int4*)(verts + w * 8))[0];
    int4 p1 = ((const int4*)(verts + w * 8))[1];
    int v[8] = {p0.x, p0.y, p0.z, p0.w, p1.x, p1.y, p1.z, p1.w};

    int code = g_pair[w];
    int bu = code & 15, bv = code >> 4;

    float4 su = make_float4(0.f, 0.f, 0.f, 0.f);
    float4 sv = su;
    float4 smed = su;
#pragma unroll
    for (int j = 0; j < 8; j++) {
        float4 f = *(const float4*)&g_Y[(size_t)v[j] * D + lane * 4];  // Xs
        if (j == bu)      su = f;
        else if (j == bv) sv = f;
        else              smed = f4add(smed, f);
    }

    float4 Au = f4scale(f4add(sv, smed), WMED);   // -> vertex at position bu
    float4 Av = f4scale(f4add(su, smed), WMED);   // -> vertex at position bv
    float4 Am = f4scale(f4add(su, sv),   WMED);   // -> each mediator position

#pragma unroll
    for (int j = 0; j < 8; j++) {
        float4 val = (j == bu) ? Au : ((j == bv) ? Av : Am);
        red_add_v4(&out[(size_t)v[j] * D + lane * 4], val);
    }
}

// ---------------- K5: out = relu(out * dinv) ----------------
__global__ void k_final(float* __restrict__ out) {
    int i = blockIdx.x * blockDim.x + threadIdx.x;
    if (i >= NV * (D / 4)) return;
    int row = i >> 5;
    float r = g_dinv[row];
    float4 o = ((float4*)out)[i];
    o.x = fmaxf(o.x * r, 0.f);
    o.y = fmaxf(o.y * r, 0.f);
    o.z = fmaxf(o.z * r, 0.f);
    o.w = fmaxf(o.w * r, 0.f);
    ((float4*)out)[i] = o;
}

// ---------------- launcher ----------------
extern "C" void kernel_launch(void* const* d_in, const int* in_sizes, int n_in,
                              void* d_out, int out_size) {
    const float* X = nullptr;
    const float* W = nullptr;
    const float* b = nullptr;
    const int* c0 = nullptr;
    const int* c1 = nullptr;

    for (int i = 0; i < n_in; i++) {
        int s = in_sizes[i];
        if (s == NV * D)        X = (const float*)d_in[i];
        else if (s == D * D)    W = (const float*)d_in[i];
        else if (s == D)        b = (const float*)d_in[i];
        else if (s == ME * 8) { if (!c0) c0 = (const int*)d_in[i]; else c1 = (const int*)d_in[i]; }
    }
    float* out = (float*)d_out;

    k_gemm<<<(NV + 127) / 128, 256>>>(X, W, b);
    k_deginit<<<(NV + 255) / 256, 256>>>(c0, c1);
    k_edge<<<(ME * 32 + 255) / 256, 256>>>();
    k_scale<<<(NV * (D / 4) + 255) / 256, 256>>>(out);
    k_scatter<<<(ME * 32 + 255) / 256, 256>>>(out);
    k_final<<<(NV * (D / 4) + 255) / 256, 256>>>(out);
}

// round 2
// speedup vs baseline: 1.5301x; 1.5301x over previous
#include <cuda_runtime.h>

#define NV 100000
#define ME 50000
#define D  128
#define WMED (1.0f / 13.0f)

// ---------------- scratch (device globals; no runtime allocation) ----------------
__device__ float g_Y[(size_t)NV * D];   // Y (pre-scaled linear output)
__device__ float g_deg[NV];
__device__ float g_dinv[NV];
__device__ int   g_pair[ME];
__device__ const int* g_verts;          // selected vertex array (vs. 'edges')

// ---------------- helpers ----------------
__device__ __forceinline__ float4 f4add(float4 a, float4 b) {
    return make_float4(a.x + b.x, a.y + b.y, a.z + b.z, a.w + b.w);
}
__device__ __forceinline__ float4 f4scale(float4 a, float s) {
    return make_float4(a.x * s, a.y * s, a.z * s, a.w * s);
}
__device__ __forceinline__ void red_add_v4(float* p, float4 v) {
    asm volatile("red.global.add.v4.f32 [%0], {%1,%2,%3,%4};"
                 :: "l"(p), "f"(v.x), "f"(v.y), "f"(v.z), "f"(v.w) : "memory");
}
__device__ __forceinline__ float warp_sum(float v) {
#pragma unroll
    for (int o = 16; o > 0; o >>= 1) v += __shfl_xor_sync(0xffffffffu, v, o);
    return v;
}
__device__ __forceinline__ unsigned long long pack2(float a) {
    unsigned long long r;
    asm("mov.b64 %0, {%1, %1};" : "=l"(r) : "f"(a));
    return r;
}
__device__ __forceinline__ void fma2(unsigned long long& acc, unsigned long long a,
                                     unsigned long long b) {
    asm("fma.rn.f32x2 %0, %1, %2, %0;" : "+l"(acc) : "l"(a), "l"(b));
}
__device__ __forceinline__ void unpack2(unsigned long long p, float& lo, float& hi) {
    asm("mov.b64 {%0, %1}, %2;" : "=f"(lo), "=f"(hi) : "l"(p));
}

// ---------------- K1: Y = X @ W + b (fp32, FFMA2 inner loop) ----------------
// BM=128, BN=128, BK=32, 256 threads, 8x8 per-thread register tile.
__global__ void __launch_bounds__(256) k_gemm(const float* __restrict__ X,
                                              const float* __restrict__ Wm,
                                              const float* __restrict__ bias) {
    __shared__ float sA[32][132];   // transposed X tile: sA[k][row]
    __shared__ float sB[32][132];   // W tile: sB[k][col]
    const int tid  = threadIdx.x;
    const int row0 = blockIdx.x * 128;
    const int tx   = tid & 15;      // col group
    const int ty   = tid >> 4;      // row group

    // acc2[r][cp]: packed pair of fp32 accumulators.
    // cp 0,1 -> cols tx*4 + {0,1},{2,3};  cp 2,3 -> cols 64+tx*4 + {0,1},{2,3}
    unsigned long long acc2[8][4];
#pragma unroll
    for (int r = 0; r < 8; r++)
#pragma unroll
        for (int c = 0; c < 4; c++) acc2[r][c] = 0ull;

    for (int k0 = 0; k0 < D; k0 += 32) {
#pragma unroll
        for (int i = 0; i < 4; i++) {
            int idx = tid + i * 256;          // 0..1023 float4s
            int r   = idx >> 3;               // 0..127 row
            int kq  = idx & 7;                // float4 along k
            int gr  = row0 + r;
            float4 xv = make_float4(0.f, 0.f, 0.f, 0.f);
            if (gr < NV) xv = *(const float4*)&X[(size_t)gr * D + k0 + kq * 4];
            sA[kq * 4 + 0][r] = xv.x;
            sA[kq * 4 + 1][r] = xv.y;
            sA[kq * 4 + 2][r] = xv.z;
            sA[kq * 4 + 3][r] = xv.w;

            int kk = idx >> 5;                // 0..31 k
            int cq = idx & 31;                // float4 along col
            *(float4*)&sB[kk][cq * 4] = *(const float4*)&Wm[(size_t)(k0 + kk) * D + cq * 4];
        }
        __syncthreads();

#pragma unroll 8
        for (int k = 0; k < 32; k++) {
            float4 a0 = *(const float4*)&sA[k][ty * 4];
            float4 a1 = *(const float4*)&sA[k][64 + ty * 4];
            ulonglong2 bq0 = *(const ulonglong2*)&sB[k][tx * 4];
            ulonglong2 bq1 = *(const ulonglong2*)&sB[k][64 + tx * 4];
            unsigned long long b2[4] = {bq0.x, bq0.y, bq1.x, bq1.y};
            float a[8] = {a0.x, a0.y, a0.z, a0.w, a1.x, a1.y, a1.z, a1.w};
#pragma unroll
            for (int r = 0; r < 8; r++) {
                unsigned long long aa = pack2(a[r]);
#pragma unroll
                for (int c = 0; c < 4; c++) fma2(acc2[r][c], aa, b2[c]);
            }
        }
        __syncthreads();
    }

    float4 bv0 = *(const float4*)&bias[tx * 4];
    float4 bv1 = *(const float4*)&bias[64 + tx * 4];
#pragma unroll
    for (int r = 0; r < 8; r++) {
        int lr = (r < 4) ? (ty * 4 + r) : (64 + ty * 4 + (r - 4));
        int gr = row0 + lr;
        if (gr >= NV) continue;
        float o[8];
#pragma unroll
        for (int c = 0; c < 4; c++) unpack2(acc2[r][c], o[2 * c], o[2 * c + 1]);
        float4 o0 = make_float4(o[0] + bv0.x, o[1] + bv0.y, o[2] + bv0.z, o[3] + bv0.w);
        float4 o1 = make_float4(o[4] + bv1.x, o[5] + bv1.y, o[6] + bv1.z, o[7] + bv1.w);
        *(float4*)&g_Y[(size_t)gr * D + tx * 4]      = o0;
        *(float4*)&g_Y[(size_t)gr * D + 64 + tx * 4] = o1;
    }
}

// ---------------- K0: deg init + vertex-array selection ----------------
__global__ void k_deginit(const int* __restrict__ c0, const int* __restrict__ c1) {
    int i = blockIdx.x * blockDim.x + threadIdx.x;
    if (i < NV) g_deg[i] = 1.0f;
    if (i == 0) {
        // 'edges' = repeat(arange(M), 8): first 8 entries 0, next 8 entries 1.
        bool c0_is_edges = (c0[0] == 0 && c0[1] == 0 && c0[8] == 1 && c0[9] == 1);
        g_verts = c0_is_edges ? c1 : c0;
    }
}

// ---------------- K2: per-hyperedge argmax pair + degree atomics ----------------
__global__ void __launch_bounds__(256) k_edge() {
    int w    = (blockIdx.x * blockDim.x + threadIdx.x) >> 5;
    int lane = threadIdx.x & 31;
    if (w >= ME) return;
    const int* verts = g_verts;

    int4 p0 = ((const int4*)(verts + w * 8))[0];
    int4 p1 = ((const int4*)(verts + w * 8))[1];
    int v[8] = {p0.x, p0.y, p0.z, p0.w, p1.x, p1.y, p1.z, p1.w};

    float4 f[8];
#pragma unroll
    for (int j = 0; j < 8; j++)
        f[j] = *(const float4*)&g_Y[(size_t)v[j] * D + lane * 4];

    float sq[8];
#pragma unroll
    for (int j = 0; j < 8; j++)
        sq[j] = warp_sum(f[j].x * f[j].x + f[j].y * f[j].y +
                         f[j].z * f[j].z + f[j].w * f[j].w);

    float best = -1e30f;
    int bu = 0, bv = 1;
#pragma unroll
    for (int j = 0; j < 8; j++) {
#pragma unroll
        for (int l = j + 1; l < 8; l++) {
            float d = warp_sum(f[j].x * f[l].x + f[j].y * f[l].y +
                               f[j].z * f[l].z + f[j].w * f[l].w);
            float d2 = sq[j] + sq[l] - 2.0f * d;
            if (d2 > best) { best = d2; bu = j; bv = l; }   // first-occurrence, row-major
        }
    }

    // degree atomics: lane j<8 handles vertex j. Avoid dynamic register index.
    int myv = v[0];
#pragma unroll
    for (int j = 1; j < 8; j++) if (lane == j) myv = v[j];
    if (lane < 8) {
        float wd = (lane == bu || lane == bv) ? 7.0f * WMED : 2.0f * WMED;
        atomicAdd(&g_deg[myv], wd);
    }
    if (lane == 0) g_pair[w] = bu | (bv << 4);
}

// ---------------- K3: dinv = rsqrt(deg) (refined) ----------------
__global__ void k_dinv() {
    int i = blockIdx.x * blockDim.x + threadIdx.x;
    if (i >= NV) return;
    float dg = g_deg[i];
    float rs = rsqrtf(dg);
    rs = rs * (1.5f - 0.5f * dg * rs * rs);          // Newton refine
    g_dinv[i] = rs;
}

// ---------------- K4: scatter graph-edge contributions (out starts at 0) ----------------
__global__ void __launch_bounds__(256) k_scatter(float* __restrict__ out) {
    int w    = (blockIdx.x * blockDim.x + threadIdx.x) >> 5;
    int lane = threadIdx.x & 31;
    if (w >= ME) return;
    const int* verts = g_verts;

    int4 p0 = ((const int4*)(verts + w * 8))[0];
    int4 p1 = ((const int4*)(verts + w * 8))[1];
    int v[8] = {p0.x, p0.y, p0.z, p0.w, p1.x, p1.y, p1.z, p1.w};

    // fetch dinv for the 8 member vertices: lane j<8 loads one, broadcast.
    int myv = v[0];
#pragma unroll
    for (int j = 1; j < 8; j++) if (lane == j) myv = v[j];
    float mydinv = (lane < 8) ? g_dinv[myv] : 0.f;
    float dv[8];
#pragma unroll
    for (int j = 0; j < 8; j++) dv[j] = __shfl_sync(0xffffffffu, mydinv, j);

    int code = g_pair[w];
    int bu = code & 15, bv = code >> 4;

    float4 su = make_float4(0.f, 0.f, 0.f, 0.f);
    float4 sv = su;
    float4 smed = su;
#pragma unroll
    for (int j = 0; j < 8; j++) {
        float4 f = *(const float4*)&g_Y[(size_t)v[j] * D + lane * 4];
        f = f4scale(f, dv[j]);                      // Xs row
        if (j == bu)      su = f;
        else if (j == bv) sv = f;
        else              smed = f4add(smed, f);
    }

    float4 Au = f4scale(f4add(sv, smed), WMED);   // -> vertex at position bu
    float4 Av = f4scale(f4add(su, smed), WMED);   // -> vertex at position bv
    float4 Am = f4scale(f4add(su, sv),   WMED);   // -> each mediator position

#pragma unroll
    for (int j = 0; j < 8; j++) {
        float4 val = (j == bu) ? Au : ((j == bv) ? Av : Am);
        red_add_v4(&out[(size_t)v[j] * D + lane * 4], val);
    }
}

// ---------------- K5: out = relu((out + Y*dinv) * dinv) ----------------
__global__ void k_final(float* __restrict__ out) {
    int i = blockIdx.x * blockDim.x + threadIdx.x;
    if (i >= NV * (D / 4)) return;
    int row = i >> 5;
    float r = g_dinv[row];
    float4 o = ((float4*)out)[i];
    float4 y = ((const float4*)g_Y)[i];
    o.x = fmaxf((o.x + y.x * r) * r, 0.f);
    o.y = fmaxf((o.y + y.y * r) * r, 0.f);
    o.z = fmaxf((o.z + y.z * r) * r, 0.f);
    o.w = fmaxf((o.w + y.w * r) * r, 0.f);
    ((float4*)out)[i] = o;
}

// ---------------- launcher ----------------
extern "C" void kernel_launch(void* const* d_in, const int* in_sizes, int n_in,
                              void* d_out, int out_size) {
    const float* X = nullptr;
    const float* W = nullptr;
    const float* b = nullptr;
    const int* c0 = nullptr;
    const int* c1 = nullptr;

    for (int i = 0; i < n_in; i++) {
        int s = in_sizes[i];
        if (s == NV * D)        X = (const float*)d_in[i];
        else if (s == D * D)    W = (const float*)d_in[i];
        else if (s == D)        b = (const float*)d_in[i];
        else if (s == ME * 8) { if (!c0) c0 = (const int*)d_in[i]; else c1 = (const int*)d_in[i]; }
    }
    float* out = (float*)d_out;

    cudaMemsetAsync(out, 0, (size_t)NV * D * sizeof(float), 0);
    k_gemm<<<(NV + 127) / 128, 256>>>(X, W, b);
    k_deginit<<<(NV + 255) / 256, 256>>>(c0, c1);
    k_edge<<<(ME * 32 + 255) / 256, 256>>>();
    k_dinv<<<(NV + 255) / 256, 256>>>();
    k_scatter<<<(ME * 32 + 255) / 256, 256>>>(out);
    k_final<<<(NV * (D / 4) + 255) / 256, 256>>>(out);
}

// round 3
// speedup vs baseline: 1.5338x; 1.0024x over previous
#include <cuda_runtime.h>

#define NV 100000
#define ME 50000
#define D  128
#define WMED (1.0f / 13.0f)

// ---------------- scratch (device globals; no runtime allocation) ----------------
__device__ float g_Y[(size_t)NV * D];   // Y (pre-scaled linear output)
__device__ float g_deg[NV];             // extra degree (actual deg = 1 + g_deg); memset 0
__device__ int   g_pair[ME];

// ---------------- helpers ----------------
__device__ __forceinline__ float4 f4add(float4 a, float4 b) {
    return make_float4(a.x + b.x, a.y + b.y, a.z + b.z, a.w + b.w);
}
__device__ __forceinline__ float4 f4scale(float4 a, float s) {
    return make_float4(a.x * s, a.y * s, a.z * s, a.w * s);
}
__device__ __forceinline__ void red_add_v4(float* p, float4 v) {
    asm volatile("red.global.add.v4.f32 [%0], {%1,%2,%3,%4};"
                 :: "l"(p), "f"(v.x), "f"(v.y), "f"(v.z), "f"(v.w) : "memory");
}
__device__ __forceinline__ float warp_sum(float v) {
#pragma unroll
    for (int o = 16; o > 0; o >>= 1) v += __shfl_xor_sync(0xffffffffu, v, o);
    return v;
}
__device__ __forceinline__ unsigned long long pack2(float a) {
    unsigned long long r;
    asm("mov.b64 %0, {%1, %1};" : "=l"(r) : "f"(a));
    return r;
}
__device__ __forceinline__ void fma2(unsigned long long& acc, unsigned long long a,
                                     unsigned long long b) {
    asm("fma.rn.f32x2 %0, %1, %2, %0;" : "+l"(acc) : "l"(a), "l"(b));
}
__device__ __forceinline__ void unpack2(unsigned long long p, float& lo, float& hi) {
    asm("mov.b64 {%0, %1}, %2;" : "=f"(lo), "=f"(hi) : "l"(p));
}
// refined reciprocal sqrt — MUST be the same sequence at every use site
__device__ __forceinline__ float rsqrt_ref(float dg) {
    float rs = rsqrtf(dg);
    return rs * (1.5f - 0.5f * dg * rs * rs);
}
// pick the vertex array ('edges' = repeat(arange(M),8) has a fixed signature)
__device__ __forceinline__ const int* pick_verts(const int* __restrict__ c0,
                                                 const int* __restrict__ c1) {
    bool c0_is_edges = (c0[0] == 0 && c0[1] == 0 && c0[8] == 1 && c0[9] == 1);
    return c0_is_edges ? c1 : c0;
}

// ---------------- K1: Y = X @ W + b (fp32, FFMA2 inner loop) ----------------
// BM=128, BN=128, BK=32, 256 threads, 8x8 per-thread register tile.
__global__ void __launch_bounds__(256) k_gemm(const float* __restrict__ X,
                                              const float* __restrict__ Wm,
                                              const float* __restrict__ bias) {
    __shared__ float sA[32][132];   // transposed X tile: sA[k][row]
    __shared__ float sB[32][132];   // W tile: sB[k][col]
    const int tid  = threadIdx.x;
    const int row0 = blockIdx.x * 128;
    const int tx   = tid & 15;      // col group
    const int ty   = tid >> 4;      // row group

    unsigned long long acc2[8][4];
#pragma unroll
    for (int r = 0; r < 8; r++)
#pragma unroll
        for (int c = 0; c < 4; c++) acc2[r][c] = 0ull;

    for (int k0 = 0; k0 < D; k0 += 32) {
#pragma unroll
        for (int i = 0; i < 4; i++) {
            int idx = tid + i * 256;          // 0..1023 float4s
            int r   = idx >> 3;               // 0..127 row
            int kq  = idx & 7;                // float4 along k
            int gr  = row0 + r;
            float4 xv = make_float4(0.f, 0.f, 0.f, 0.f);
            if (gr < NV) xv = *(const float4*)&X[(size_t)gr * D + k0 + kq * 4];
            sA[kq * 4 + 0][r] = xv.x;
            sA[kq * 4 + 1][r] = xv.y;
            sA[kq * 4 + 2][r] = xv.z;
            sA[kq * 4 + 3][r] = xv.w;

            int kk = idx >> 5;                // 0..31 k
            int cq = idx & 31;                // float4 along col
            *(float4*)&sB[kk][cq * 4] = *(const float4*)&Wm[(size_t)(k0 + kk) * D + cq * 4];
        }
        __syncthreads();

#pragma unroll 8
        for (int k = 0; k < 32; k++) {
            float4 a0 = *(const float4*)&sA[k][ty * 4];
            float4 a1 = *(const float4*)&sA[k][64 + ty * 4];
            ulonglong2 bq0 = *(const ulonglong2*)&sB[k][tx * 4];
            ulonglong2 bq1 = *(const ulonglong2*)&sB[k][64 + tx * 4];
            unsigned long long b2[4] = {bq0.x, bq0.y, bq1.x, bq1.y};
            float a[8] = {a0.x, a0.y, a0.z, a0.w, a1.x, a1.y, a1.z, a1.w};
#pragma unroll
            for (int r = 0; r < 8; r++) {
                unsigned long long aa = pack2(a[r]);
#pragma unroll
                for (int c = 0; c < 4; c++) fma2(acc2[r][c], aa, b2[c]);
            }
        }
        __syncthreads();
    }

    float4 bv0 = *(const float4*)&bias[tx * 4];
    float4 bv1 = *(const float4*)&bias[64 + tx * 4];
#pragma unroll
    for (int r = 0; r < 8; r++) {
        int lr = (r < 4) ? (ty * 4 + r) : (64 + ty * 4 + (r - 4));
        int gr = row0 + lr;
        if (gr >= NV) continue;
        float o[8];
#pragma unroll
        for (int c = 0; c < 4; c++) unpack2(acc2[r][c], o[2 * c], o[2 * c + 1]);
        float4 o0 = make_float4(o[0] + bv0.x, o[1] + bv0.y, o[2] + bv0.z, o[3] + bv0.w);
        float4 o1 = make_float4(o[4] + bv1.x, o[5] + bv1.y, o[6] + bv1.z, o[7] + bv1.w);
        *(float4*)&g_Y[(size_t)gr * D + tx * 4]      = o0;
        *(float4*)&g_Y[(size_t)gr * D + 64 + tx * 4] = o1;
    }
}

// ---------------- K2: per-hyperedge argmax pair + degree atomics ----------------
__global__ void __launch_bounds__(256) k_edge(const int* __restrict__ c0,
                                              const int* __restrict__ c1) {
    int w    = (blockIdx.x * blockDim.x + threadIdx.x) >> 5;
    int lane = threadIdx.x & 31;
    if (w >= ME) return;
    const int* verts = pick_verts(c0, c1);

    int4 p0 = ((const int4*)(verts + w * 8))[0];
    int4 p1 = ((const int4*)(verts + w * 8))[1];
    int v[8] = {p0.x, p0.y, p0.z, p0.w, p1.x, p1.y, p1.z, p1.w};

    float4 f[8];
#pragma unroll
    for (int j = 0; j < 8; j++)
        f[j] = *(const float4*)&g_Y[(size_t)v[j] * D + lane * 4];

    float sq[8];
#pragma unroll
    for (int j = 0; j < 8; j++)
        sq[j] = warp_sum(f[j].x * f[j].x + f[j].y * f[j].y +
                         f[j].z * f[j].z + f[j].w * f[j].w);

    float best = -1e30f;
    int bu = 0, bv = 1;
#pragma unroll
    for (int j = 0; j < 8; j++) {
#pragma unroll
        for (int l = j + 1; l < 8; l++) {
            float d = warp_sum(f[j].x * f[l].x + f[j].y * f[l].y +
                               f[j].z * f[l].z + f[j].w * f[l].w);
            float d2 = sq[j] + sq[l] - 2.0f * d;
            if (d2 > best) { best = d2; bu = j; bv = l; }   // first-occurrence, row-major
        }
    }

    // degree atomics: lane j<8 handles vertex j (no dynamic register index).
    int myv = v[0];
#pragma unroll
    for (int j = 1; j < 8; j++) if (lane == j) myv = v[j];
    if (lane < 8) {
        float wd = (lane == bu || lane == bv) ? 7.0f * WMED : 2.0f * WMED;
        atomicAdd(&g_deg[myv], wd);
    }
    if (lane == 0) g_pair[w] = bu | (bv << 4);
}

// ---------------- K3: scatter graph-edge contributions (out starts at 0) ----------------
__global__ void __launch_bounds__(256) k_scatter(float* __restrict__ out,
                                                 const int* __restrict__ c0,
                                                 const int* __restrict__ c1) {
    int w    = (blockIdx.x * blockDim.x + threadIdx.x) >> 5;
    int lane = threadIdx.x & 31;
    if (w >= ME) return;
    const int* verts = pick_verts(c0, c1);

    int4 p0 = ((const int4*)(verts + w * 8))[0];
    int4 p1 = ((const int4*)(verts + w * 8))[1];
    int v[8] = {p0.x, p0.y, p0.z, p0.w, p1.x, p1.y, p1.z, p1.w};

    // dinv for the 8 member vertices: lane j<8 computes one, broadcast.
    int myv = v[0];
#pragma unroll
    for (int j = 1; j < 8; j++) if (lane == j) myv = v[j];
    float mydinv = 0.f;
    if (lane < 8) mydinv = rsqrt_ref(1.0f + g_deg[myv]);
    float dv[8];
#pragma unroll
    for (int j = 0; j < 8; j++) dv[j] = __shfl_sync(0xffffffffu, mydinv, j);

    int code = g_pair[w];
    int bu = code & 15, bv = code >> 4;

    float4 su = make_float4(0.f, 0.f, 0.f, 0.f);
    float4 sv = su;
    float4 smed = su;
#pragma unroll
    for (int j = 0; j < 8; j++) {
        float4 f = *(const float4*)&g_Y[(size_t)v[j] * D + lane * 4];
        f = f4scale(f, dv[j]);                      // Xs row
        if (j == bu)      su = f;
        else if (j == bv) sv = f;
        else              smed = f4add(smed, f);
    }

    float4 Au = f4scale(f4add(sv, smed), WMED);   // -> vertex at position bu
    float4 Av = f4scale(f4add(su, smed), WMED);   // -> vertex at position bv
    float4 Am = f4scale(f4add(su, sv),   WMED);   // -> each mediator position

#pragma unroll
    for (int j = 0; j < 8; j++) {
        float4 val = (j == bu) ? Au : ((j == bv) ? Av : Am);
        red_add_v4(&out[(size_t)v[j] * D + lane * 4], val);
    }
}

// ---------------- K4: out = relu((out + Y*dinv) * dinv) ----------------
__global__ void k_final(float* __restrict__ out) {
    int i = blockIdx.x * blockDim.x + threadIdx.x;
    if (i >= NV * (D / 4)) return;
    int row = i >> 5;
    float r = rsqrt_ref(1.0f + g_deg[row]);
    float4 o = ((float4*)out)[i];
    float4 y = ((const float4*)g_Y)[i];
    o.x = fmaxf((o.x + y.x * r) * r, 0.f);
    o.y = fmaxf((o.y + y.y * r) * r, 0.f);
    o.z = fmaxf((o.z + y.z * r) * r, 0.f);
    o.w = fmaxf((o.w + y.w * r) * r, 0.f);
    ((float4*)out)[i] = o;
}

// ---------------- launcher ----------------
extern "C" void kernel_launch(void* const* d_in, const int* in_sizes, int n_in,
                              void* d_out, int out_size) {
    const float* X = nullptr;
    const float* W = nullptr;
    const float* b = nullptr;
    const int* c0 = nullptr;
    const int* c1 = nullptr;

    for (int i = 0; i < n_in; i++) {
        int s = in_sizes[i];
        if (s == NV * D)        X = (const float*)d_in[i];
        else if (s == D * D)    W = (const float*)d_in[i];
        else if (s == D)        b = (const float*)d_in[i];
        else if (s == ME * 8) { if (!c0) c0 = (const int*)d_in[i]; else c1 = (const int*)d_in[i]; }
    }
    float* out = (float*)d_out;

    void* degPtr = nullptr;
    cudaGetSymbolAddress(&degPtr, g_deg);

    cudaMemsetAsync(degPtr, 0, (size_t)NV * sizeof(float), 0);
    cudaMemsetAsync(out, 0, (size_t)NV * D * sizeof(float), 0);
    k_gemm<<<(NV + 127) / 128, 256>>>(X, W, b);
    k_edge<<<(ME * 32 + 255) / 256, 256>>>(c0, c1);
    k_scatter<<<(ME * 32 + 255) / 256, 256>>>(out, c0, c1);
    k_final<<<(NV * (D / 4) + 255) / 256, 256>>>(out);
}